// round 9
// baseline (speedup 1.0000x reference)
#include <cuda_runtime.h>
#include <math.h>
#include <float.h>

#define D 256
#define MAX_S 20000
#define GTM 64    // rows per block in epilogue GEMM

// Scratch (static device globals — no allocation)
__device__ float g_pooled[(size_t)MAX_S * D];  // normalized: sum(gate_norm * x)
__device__ float g_sumg[MAX_S];                // sum(gate_norm) = d/(d+eps)
__device__ int   g_segstart[MAX_S + 1];

// --- Kernel 1: segment boundaries by marking (index sorted, one coalesced pass) ---
__global__ void segstart_kernel(const int* __restrict__ index, int N, int S) {
    int i = blockIdx.x * blockDim.x + threadIdx.x;
    if (i >= N) return;
    int cur = index[i];
    int prev = (i == 0) ? -1 : index[i - 1];
    for (int s = prev + 1; s <= cur; s++) g_segstart[s] = i;
    if (i == N - 1)
        for (int s = cur + 1; s <= S; s++) g_segstart[s] = N;
}

// --- Kernel 2: fused gate + online softmax + weighted pooling ---
// One warp per segment, FOUR nodes per iteration: 4 interleaved shfl-allreduce
// chains amortize the 5-stage butterfly latency; 16 LDG.128 in flight per warp.
// Remainder nodes use clamped row loads with e forced to 0 (h = -FLT_MAX).
__global__ __launch_bounds__(128) void fused_kernel(
    const float* __restrict__ x, const float* __restrict__ weights,
    const float* __restrict__ Wg, const float* __restrict__ bg,
    const float* __restrict__ p, int S)
{
    int lane = threadIdx.x & 31;
    int seg = (blockIdx.x * blockDim.x + threadIdx.x) >> 5;
    if (seg >= S) return;

    const float4* wg4 = (const float4*)Wg;
    float4 w1 = wg4[lane], w2 = wg4[lane + 32];
    float bgv = bg[0], pv = p[0];

    int a = g_segstart[seg], b = g_segstart[seg + 1];

    float m = -FLT_MAX, d = 0.f;
    float4 A1 = make_float4(0.f, 0.f, 0.f, 0.f);
    float4 A2 = make_float4(0.f, 0.f, 0.f, 0.f);

    float4 ua[4], ub[4]; float qw[4];
    if (a < b) {
        #pragma unroll
        for (int j = 0; j < 4; j++) {
            int n = min(a + j, b - 1);           // clamp: dup rows get e=0
            const float4* r = (const float4*)(x + (size_t)n * D);
            ua[j] = __ldcs(r + lane); ub[j] = __ldcs(r + lane + 32);
            qw[j] = weights[n];
        }
    }

    for (int n0 = a; n0 < b; n0 += 4) {
        float4 ca[4], cb[4]; float cw[4];
        #pragma unroll
        for (int j = 0; j < 4; j++) { ca[j] = ua[j]; cb[j] = ub[j]; cw[j] = qw[j]; }

        if (n0 + 4 < b) {   // prefetch next quad while reducing current
            #pragma unroll
            for (int j = 0; j < 4; j++) {
                int n = min(n0 + 4 + j, b - 1);
                const float4* r = (const float4*)(x + (size_t)n * D);
                ua[j] = __ldcs(r + lane); ub[j] = __ldcs(r + lane + 32);
                qw[j] = weights[n];
            }
        }

        float s[4];
        #pragma unroll
        for (int j = 0; j < 4; j++)
            s[j] = ca[j].x * w1.x + ca[j].y * w1.y + ca[j].z * w1.z + ca[j].w * w1.w
                 + cb[j].x * w2.x + cb[j].y * w2.y + cb[j].z * w2.z + cb[j].w * w2.w;

        #pragma unroll
        for (int o = 16; o > 0; o >>= 1) {   // 4 independent chains, pipelined
            #pragma unroll
            for (int j = 0; j < 4; j++)
                s[j] += __shfl_xor_sync(0xffffffffu, s[j], o);
        }

        float h[4];
        #pragma unroll
        for (int j = 0; j < 4; j++)
            h[j] = (n0 + j < b) ? fmaf(pv, __logf(cw[j]), s[j] + bgv) : -FLT_MAX;

        float hm = fmaxf(fmaxf(h[0], h[1]), fmaxf(h[2], h[3]));
        if (hm > m) {                         // warp-uniform; first iter always taken
            float r = __expf(m - hm);         // exp(-inf) = 0 on first iter
            m = hm; d *= r;
            A1.x *= r; A1.y *= r; A1.z *= r; A1.w *= r;
            A2.x *= r; A2.y *= r; A2.z *= r; A2.w *= r;
        }

        float e[4];
        #pragma unroll
        for (int j = 0; j < 4; j++)
            e[j] = __expf(h[j] - m);          // invalid j -> exp(-huge) = 0
        d += (e[0] + e[1]) + (e[2] + e[3]);

        #pragma unroll
        for (int j = 0; j < 4; j++) {
            A1.x = fmaf(e[j], ca[j].x, A1.x); A1.y = fmaf(e[j], ca[j].y, A1.y);
            A1.z = fmaf(e[j], ca[j].z, A1.z); A1.w = fmaf(e[j], ca[j].w, A1.w);
            A2.x = fmaf(e[j], cb[j].x, A2.x); A2.y = fmaf(e[j], cb[j].y, A2.y);
            A2.z = fmaf(e[j], cb[j].z, A2.z); A2.w = fmaf(e[j], cb[j].w, A2.w);
        }
    }

    float inv = 1.f / (d + 1e-10f);
    A1.x *= inv; A1.y *= inv; A1.z *= inv; A1.w *= inv;
    A2.x *= inv; A2.y *= inv; A2.z *= inv; A2.w *= inv;
    float4* po = (float4*)(g_pooled + (size_t)seg * D);
    po[lane] = A1; po[lane + 32] = A2;
    if (lane == 0) g_sumg[seg] = d * inv;
}

// --- Kernel 3: out = pooled_norm @ Wm + sumg * bm, packed fma.rn.f32x2 ---
// Wm value for kk+1 is prefetched across the current FMA chain so the L2-hit
// latency (~234cyc) never stalls the pipe.
__global__ __launch_bounds__(256) void gemm_kernel(
    const float* __restrict__ Wm, const float* __restrict__ bm,
    float* __restrict__ out, int S)
{
    __shared__ float As[32][GTM + 4];
    int tid = threadIdx.x;
    int row0 = blockIdx.x * GTM;

    unsigned long long acc2[GTM / 2];
    #pragma unroll
    for (int i = 0; i < GTM / 2; i++) acc2[i] = 0ull;

    float bv_next = Wm[tid];   // k=0 column value
    for (int k0 = 0; k0 < D; k0 += 32) {
        #pragma unroll
        for (int i = 0; i < GTM * 32 / 256; i++) {
            int idx = tid + i * 256;
            int r = idx >> 5, kk = idx & 31;
            int row = row0 + r;
            As[kk][r] = (row < S) ? g_pooled[(size_t)row * D + k0 + kk] : 0.f;
        }
        __syncthreads();
        #pragma unroll
        for (int kk = 0; kk < 32; kk++) {
            float bv = bv_next;
            int knext = k0 + kk + 1;
            if (knext < D) bv_next = Wm[(size_t)knext * D + tid];  // prefetch
            unsigned long long b2;
            asm("mov.b64 %0, {%1, %1};" : "=l"(b2) : "r"(__float_as_uint(bv)));
            #pragma unroll
            for (int r4 = 0; r4 < GTM; r4 += 4) {
                double2 dv = *(const double2*)&As[kk][r4];
                unsigned long long a01 = __double_as_longlong(dv.x);
                unsigned long long a23 = __double_as_longlong(dv.y);
                asm("fma.rn.f32x2 %0, %1, %2, %0;" : "+l"(acc2[r4 / 2])     : "l"(a01), "l"(b2));
                asm("fma.rn.f32x2 %0, %1, %2, %0;" : "+l"(acc2[r4 / 2 + 1]) : "l"(a23), "l"(b2));
            }
        }
        __syncthreads();
    }

    float bmv = bm[tid];
    #pragma unroll
    for (int r = 0; r < GTM; r += 2) {
        unsigned long long v = acc2[r / 2];
        float lo = __uint_as_float((unsigned)v);
        float hi = __uint_as_float((unsigned)(v >> 32));
        int row = row0 + r;
        if (row < S)     out[(size_t)row * D + tid]       = lo + g_sumg[row] * bmv;
        if (row + 1 < S) out[(size_t)(row + 1) * D + tid] = hi + g_sumg[row + 1] * bmv;
    }
}

extern "C" void kernel_launch(void* const* d_in, const int* in_sizes, int n_in,
                              void* d_out, int out_size) {
    const float* x       = (const float*)d_in[0];
    const float* weights = (const float*)d_in[1];
    const float* Wg      = (const float*)d_in[2];
    const float* bg      = (const float*)d_in[3];
    const float* Wm      = (const float*)d_in[4];
    const float* bm      = (const float*)d_in[5];
    const float* p       = (const float*)d_in[6];
    const int*   index   = (const int*)d_in[7];
    float* out = (float*)d_out;

    int N = in_sizes[7];
    int S = out_size / D;

    segstart_kernel<<<(N + 255) / 256, 256>>>(index, N, S);
    fused_kernel<<<(S * 32 + 127) / 128, 128>>>(x, weights, Wg, bg, p, S);
    gemm_kernel<<<(S + GTM - 1) / GTM, 256>>>(Wm, bm, out, S);
}

// round 15
// speedup vs baseline: 1.0198x; 1.0198x over previous
#include <cuda_runtime.h>
#include <math.h>
#include <float.h>

#define D 256
#define MAX_S 20000
#define GTM 64    // rows per block in epilogue GEMM

// Scratch (static device globals — no allocation)
__device__ float g_pooled[(size_t)MAX_S * D];  // normalized: sum(gate_norm * x)
__device__ float g_sumg[MAX_S];                // sum(gate_norm) = d/(d+eps)
__device__ int   g_segstart[MAX_S + 1];

// --- Kernel 1: segment boundaries by marking (index sorted, one coalesced pass) ---
__global__ void segstart_kernel(const int* __restrict__ index, int N, int S) {
    int i = blockIdx.x * blockDim.x + threadIdx.x;
    if (i >= N) return;
    int cur = index[i];
    int prev = (i == 0) ? -1 : index[i - 1];
    for (int s = prev + 1; s <= cur; s++) g_segstart[s] = i;
    if (i == N - 1)
        for (int s = cur + 1; s <= S; s++) g_segstart[s] = N;
}

// --- Kernel 2: fused gate + online softmax + weighted pooling ---
// One warp per segment, two nodes per iteration (proven R7 structure).
// Half-warp fold: lanes<16 reduce s0, lanes>=16 reduce s1 -> 6 SHFL per pair
// instead of 10, and one logf per lane instead of two.
__global__ __launch_bounds__(256) void fused_kernel(
    const float* __restrict__ x, const float* __restrict__ weights,
    const float* __restrict__ Wg, const float* __restrict__ bg,
    const float* __restrict__ p, int S)
{
    int lane = threadIdx.x & 31;
    int seg = (blockIdx.x * blockDim.x + threadIdx.x) >> 5;
    if (seg >= S) return;
    bool lo16 = (lane < 16);

    const float4* wg4 = (const float4*)Wg;
    float4 w1 = wg4[lane], w2 = wg4[lane + 32];
    float bgv = bg[0], pv = p[0];

    int a = g_segstart[seg], b = g_segstart[seg + 1];

    float m = -FLT_MAX, d = 0.f;
    float4 A1 = make_float4(0.f, 0.f, 0.f, 0.f);
    float4 A2 = make_float4(0.f, 0.f, 0.f, 0.f);

    float4 u0a, u0b, u1a, u1b; float q0, q1;
    if (a < b) {
        int n1 = (a + 1 < b) ? a + 1 : a;
        const float4* r0 = (const float4*)(x + (size_t)a * D);
        const float4* r1 = (const float4*)(x + (size_t)n1 * D);
        u0a = __ldcs(r0 + lane); u0b = __ldcs(r0 + lane + 32);
        u1a = __ldcs(r1 + lane); u1b = __ldcs(r1 + lane + 32);
        q0 = weights[a]; q1 = weights[n1];
    }

    for (int n = a; n < b; n += 2) {
        float4 c0a = u0a, c0b = u0b, c1a = u1a, c1b = u1b;
        float p0 = q0, p1 = q1;
        bool has2 = (n + 1 < b);

        int nn = n + 2;
        if (nn < b) {   // prefetch next pair (x streamed, read exactly once)
            int n1 = (nn + 1 < b) ? nn + 1 : nn;
            const float4* r0 = (const float4*)(x + (size_t)nn * D);
            const float4* r1 = (const float4*)(x + (size_t)n1 * D);
            u0a = __ldcs(r0 + lane); u0b = __ldcs(r0 + lane + 32);
            u1a = __ldcs(r1 + lane); u1b = __ldcs(r1 + lane + 32);
            q0 = weights[nn]; q1 = weights[n1];
        }

        float s0 = c0a.x * w1.x + c0a.y * w1.y + c0a.z * w1.z + c0a.w * w1.w
                 + c0b.x * w2.x + c0b.y * w2.y + c0b.z * w2.z + c0b.w * w2.w;
        float s1 = c1a.x * w1.x + c1a.y * w1.y + c1a.z * w1.z + c1a.w * w1.w
                 + c1b.x * w2.x + c1b.y * w2.y + c1b.z * w2.z + c1b.w * w2.w;

        // half-warp fold: give away the "other" sum's partial, keep own half
        float give = lo16 ? s1 : s0;
        float got  = __shfl_xor_sync(0xffffffffu, give, 16);
        float z = (lo16 ? s0 : s1) + got;
        #pragma unroll
        for (int o = 8; o > 0; o >>= 1) z += __shfl_xor_sync(0xffffffffu, z, o);
        // lanes<16: z = full s0 ; lanes>=16: z = full s1

        float h_own = fmaf(pv, __logf(lo16 ? p0 : p1), z + bgv);
        float h_oth = __shfl_xor_sync(0xffffffffu, h_own, 16);
        float h0 = lo16 ? h_own : h_oth;
        float h1 = lo16 ? h_oth : h_own;
        if (!has2) h1 = -FLT_MAX;

        float hm = fmaxf(h0, h1);
        if (hm > m) {                         // warp-uniform, rare after warm-up
            float r = __expf(m - hm);         // first iter: exp(-inf) = 0
            m = hm; d *= r;
            A1.x *= r; A1.y *= r; A1.z *= r; A1.w *= r;
            A2.x *= r; A2.y *= r; A2.z *= r; A2.w *= r;
        }
        float e0 = __expf(h0 - m);
        float e1 = __expf(h1 - m);            // h1=-FLT_MAX -> 0 when !has2
        d += e0 + e1;
        A1.x = fmaf(e1, c1a.x, fmaf(e0, c0a.x, A1.x));
        A1.y = fmaf(e1, c1a.y, fmaf(e0, c0a.y, A1.y));
        A1.z = fmaf(e1, c1a.z, fmaf(e0, c0a.z, A1.z));
        A1.w = fmaf(e1, c1a.w, fmaf(e0, c0a.w, A1.w));
        A2.x = fmaf(e1, c1b.x, fmaf(e0, c0b.x, A2.x));
        A2.y = fmaf(e1, c1b.y, fmaf(e0, c0b.y, A2.y));
        A2.z = fmaf(e1, c1b.z, fmaf(e0, c0b.z, A2.z));
        A2.w = fmaf(e1, c1b.w, fmaf(e0, c0b.w, A2.w));
    }

    float inv = 1.f / (d + 1e-10f);
    A1.x *= inv; A1.y *= inv; A1.z *= inv; A1.w *= inv;
    A2.x *= inv; A2.y *= inv; A2.z *= inv; A2.w *= inv;
    float4* po = (float4*)(g_pooled + (size_t)seg * D);
    po[lane] = A1; po[lane + 32] = A2;
    if (lane == 0) g_sumg[seg] = d * inv;
}

// --- Kernel 3: out = pooled_norm @ Wm + sumg * bm, packed fma.rn.f32x2 ---
// Double-buffered A tile through registers + Wm prefetch across the FMA chain:
// both global-load latencies overlap compute instead of serializing at barriers.
__global__ __launch_bounds__(256) void gemm_kernel(
    const float* __restrict__ Wm, const float* __restrict__ bm,
    float* __restrict__ out, int S)
{
    __shared__ float As[32][GTM + 4];
    int tid = threadIdx.x;
    int row0 = blockIdx.x * GTM;
    const int LPT = GTM * 32 / 256;   // tile loads per thread = 8

    unsigned long long acc2[GTM / 2];
    #pragma unroll
    for (int i = 0; i < GTM / 2; i++) acc2[i] = 0ull;

    // preload tile k0=0 into registers
    float regbuf[LPT];
    #pragma unroll
    for (int i = 0; i < LPT; i++) {
        int idx = tid + i * 256;
        int r = idx >> 5, kk = idx & 31;
        int row = row0 + r;
        regbuf[i] = (row < S) ? g_pooled[(size_t)row * D + kk] : 0.f;
    }

    float bv_next = Wm[tid];   // k=0 column value
    for (int k0 = 0; k0 < D; k0 += 32) {
        __syncthreads();               // As consumers of previous tile done
        #pragma unroll
        for (int i = 0; i < LPT; i++) {
            int idx = tid + i * 256;
            As[idx & 31][idx >> 5] = regbuf[i];
        }
        __syncthreads();
        if (k0 + 32 < D) {             // prefetch next tile during compute
            #pragma unroll
            for (int i = 0; i < LPT; i++) {
                int idx = tid + i * 256;
                int r = idx >> 5, kk = idx & 31;
                int row = row0 + r;
                regbuf[i] = (row < S) ? g_pooled[(size_t)row * D + k0 + 32 + kk] : 0.f;
            }
        }
        #pragma unroll
        for (int kk = 0; kk < 32; kk++) {
            float bv = bv_next;
            int knext = k0 + kk + 1;
            if (knext < D) bv_next = Wm[(size_t)knext * D + tid];  // prefetch
            unsigned long long b2;
            asm("mov.b64 %0, {%1, %1};" : "=l"(b2) : "r"(__float_as_uint(bv)));
            #pragma unroll
            for (int r4 = 0; r4 < GTM; r4 += 4) {
                double2 dv = *(const double2*)&As[kk][r4];
                unsigned long long a01 = __double_as_longlong(dv.x);
                unsigned long long a23 = __double_as_longlong(dv.y);
                asm("fma.rn.f32x2 %0, %1, %2, %0;" : "+l"(acc2[r4 / 2])     : "l"(a01), "l"(b2));
                asm("fma.rn.f32x2 %0, %1, %2, %0;" : "+l"(acc2[r4 / 2 + 1]) : "l"(a23), "l"(b2));
            }
        }
    }

    float bmv = bm[tid];
    #pragma unroll
    for (int r = 0; r < GTM; r += 2) {
        unsigned long long v = acc2[r / 2];
        float lo = __uint_as_float((unsigned)v);
        float hi = __uint_as_float((unsigned)(v >> 32));
        int row = row0 + r;
        if (row < S)     out[(size_t)row * D + tid]       = lo + g_sumg[row] * bmv;
        if (row + 1 < S) out[(size_t)(row + 1) * D + tid] = hi + g_sumg[row + 1] * bmv;
    }
}

extern "C" void kernel_launch(void* const* d_in, const int* in_sizes, int n_in,
                              void* d_out, int out_size) {
    const float* x       = (const float*)d_in[0];
    const float* weights = (const float*)d_in[1];
    const float* Wg      = (const float*)d_in[2];
    const float* bg      = (const float*)d_in[3];
    const float* Wm      = (const float*)d_in[4];
    const float* bm      = (const float*)d_in[5];
    const float* p       = (const float*)d_in[6];
    const int*   index   = (const int*)d_in[7];
    float* out = (float*)d_out;

    int N = in_sizes[7];
    int S = out_size / D;

    segstart_kernel<<<(N + 255) / 256, 256>>>(index, N, S);
    fused_kernel<<<(S * 32 + 255) / 256, 256>>>(x, weights, Wg, bg, p, S);
    gemm_kernel<<<(S + GTM - 1) / GTM, 256>>>(Wm, bm, out, S);
}

// round 17
// speedup vs baseline: 1.3978x; 1.3707x over previous
#include <cuda_runtime.h>
#include <math.h>
#include <float.h>

#define D 256
#define MAX_S 20000
#define GTM 64    // rows per block in epilogue GEMM

// Scratch (static device globals — no allocation)
__device__ float g_pooled[(size_t)MAX_S * D];  // normalized: sum(gate_norm * x)
__device__ float g_sumg[MAX_S];                // sum(gate_norm) = d/(d+eps)
__device__ int   g_segstart[MAX_S + 1];

// --- Kernel 1: segment boundaries by marking (index sorted, one coalesced pass) ---
__global__ void segstart_kernel(const int* __restrict__ index, int N, int S) {
    int i = blockIdx.x * blockDim.x + threadIdx.x;
    if (i >= N) return;
    int cur = index[i];
    int prev = (i == 0) ? -1 : index[i - 1];
    for (int s = prev + 1; s <= cur; s++) g_segstart[s] = i;
    if (i == N - 1)
        for (int s = cur + 1; s <= S; s++) g_segstart[s] = N;
}

// --- Kernel 2: fused gate + online softmax + weighted pooling ---
// One warp per segment, two nodes per iteration with interleaved shfl chains
// (exact R7 structure). Block size 128: reg granularity gives >= warps/SM vs
// 256 at any plausible reg count, and 4-segment blocks balance better.
__global__ __launch_bounds__(128) void fused_kernel(
    const float* __restrict__ x, const float* __restrict__ weights,
    const float* __restrict__ Wg, const float* __restrict__ bg,
    const float* __restrict__ p, int S)
{
    int lane = threadIdx.x & 31;
    int seg = (blockIdx.x * blockDim.x + threadIdx.x) >> 5;
    if (seg >= S) return;

    const float4* wg4 = (const float4*)Wg;
    float4 w1 = wg4[lane], w2 = wg4[lane + 32];
    float bgv = bg[0], pv = p[0];

    int a = g_segstart[seg], b = g_segstart[seg + 1];

    float m = -FLT_MAX, d = 0.f;
    float4 A1 = make_float4(0.f, 0.f, 0.f, 0.f);
    float4 A2 = make_float4(0.f, 0.f, 0.f, 0.f);

    float4 u0a, u0b, u1a, u1b; float q0, q1;
    if (a < b) {
        int n1 = (a + 1 < b) ? a + 1 : a;
        const float4* r0 = (const float4*)(x + (size_t)a * D);
        const float4* r1 = (const float4*)(x + (size_t)n1 * D);
        u0a = __ldcs(r0 + lane); u0b = __ldcs(r0 + lane + 32);
        u1a = __ldcs(r1 + lane); u1b = __ldcs(r1 + lane + 32);
        q0 = weights[a]; q1 = weights[n1];
    }

    for (int n = a; n < b; n += 2) {
        float4 c0a = u0a, c0b = u0b, c1a = u1a, c1b = u1b;
        float p0 = q0, p1 = q1;
        bool has2 = (n + 1 < b);

        int nn = n + 2;
        if (nn < b) {   // prefetch next pair (x streamed, read exactly once)
            int n1 = (nn + 1 < b) ? nn + 1 : nn;
            const float4* r0 = (const float4*)(x + (size_t)nn * D);
            const float4* r1 = (const float4*)(x + (size_t)n1 * D);
            u0a = __ldcs(r0 + lane); u0b = __ldcs(r0 + lane + 32);
            u1a = __ldcs(r1 + lane); u1b = __ldcs(r1 + lane + 32);
            q0 = weights[nn]; q1 = weights[n1];
        }

        float s0 = c0a.x * w1.x + c0a.y * w1.y + c0a.z * w1.z + c0a.w * w1.w
                 + c0b.x * w2.x + c0b.y * w2.y + c0b.z * w2.z + c0b.w * w2.w;
        float s1 = c1a.x * w1.x + c1a.y * w1.y + c1a.z * w1.z + c1a.w * w1.w
                 + c1b.x * w2.x + c1b.y * w2.y + c1b.z * w2.z + c1b.w * w2.w;
        #pragma unroll
        for (int o = 16; o > 0; o >>= 1) {   // two independent chains, pipelined
            s0 += __shfl_xor_sync(0xffffffffu, s0, o);
            s1 += __shfl_xor_sync(0xffffffffu, s1, o);
        }

        float h0 = fmaf(pv, __logf(p0), s0 + bgv);
        float h1 = has2 ? fmaf(pv, __logf(p1), s1 + bgv) : -FLT_MAX;
        float hm = fmaxf(h0, h1);
        if (hm > m) {                         // warp-uniform, rare after warm-up
            float r = __expf(m - hm);         // first iter: exp(-inf) = 0
            m = hm; d *= r;
            A1.x *= r; A1.y *= r; A1.z *= r; A1.w *= r;
            A2.x *= r; A2.y *= r; A2.z *= r; A2.w *= r;
        }
        float e0 = __expf(h0 - m);
        float e1 = __expf(h1 - m);            // h1=-FLT_MAX -> 0 when !has2
        d += e0 + e1;
        A1.x = fmaf(e1, c1a.x, fmaf(e0, c0a.x, A1.x));
        A1.y = fmaf(e1, c1a.y, fmaf(e0, c0a.y, A1.y));
        A1.z = fmaf(e1, c1a.z, fmaf(e0, c0a.z, A1.z));
        A1.w = fmaf(e1, c1a.w, fmaf(e0, c0a.w, A1.w));
        A2.x = fmaf(e1, c1b.x, fmaf(e0, c0b.x, A2.x));
        A2.y = fmaf(e1, c1b.y, fmaf(e0, c0b.y, A2.y));
        A2.z = fmaf(e1, c1b.z, fmaf(e0, c0b.z, A2.z));
        A2.w = fmaf(e1, c1b.w, fmaf(e0, c0b.w, A2.w));
    }

    float inv = 1.f / (d + 1e-10f);
    A1.x *= inv; A1.y *= inv; A1.z *= inv; A1.w *= inv;
    A2.x *= inv; A2.y *= inv; A2.z *= inv; A2.w *= inv;
    float4* po = (float4*)(g_pooled + (size_t)seg * D);
    po[lane] = A1; po[lane + 32] = A2;
    if (lane == 0) g_sumg[seg] = d * inv;
}

// --- Kernel 3: out = pooled_norm @ Wm + sumg * bm, packed fma.rn.f32x2 ---
// Exact R7 version: Wm loaded inside the unrolled kk loop so ptxas batches
// the loads itself (manual bv_next prefetch serialized them and regressed).
__global__ __launch_bounds__(256) void gemm_kernel(
    const float* __restrict__ Wm, const float* __restrict__ bm,
    float* __restrict__ out, int S)
{
    __shared__ float As[32][GTM + 4];
    int tid = threadIdx.x;
    int row0 = blockIdx.x * GTM;

    unsigned long long acc2[GTM / 2];
    #pragma unroll
    for (int i = 0; i < GTM / 2; i++) acc2[i] = 0ull;

    for (int k0 = 0; k0 < D; k0 += 32) {
        #pragma unroll
        for (int i = 0; i < GTM * 32 / 256; i++) {
            int idx = tid + i * 256;
            int r = idx >> 5, kk = idx & 31;
            int row = row0 + r;
            As[kk][r] = (row < S) ? g_pooled[(size_t)row * D + k0 + kk] : 0.f;
        }
        __syncthreads();
        #pragma unroll
        for (int kk = 0; kk < 32; kk++) {
            float bv = Wm[(size_t)(k0 + kk) * D + tid];
            unsigned long long b2;
            asm("mov.b64 %0, {%1, %1};" : "=l"(b2) : "r"(__float_as_uint(bv)));
            #pragma unroll
            for (int r4 = 0; r4 < GTM; r4 += 4) {
                double2 dv = *(const double2*)&As[kk][r4];
                unsigned long long a01 = __double_as_longlong(dv.x);
                unsigned long long a23 = __double_as_longlong(dv.y);
                asm("fma.rn.f32x2 %0, %1, %2, %0;" : "+l"(acc2[r4 / 2])     : "l"(a01), "l"(b2));
                asm("fma.rn.f32x2 %0, %1, %2, %0;" : "+l"(acc2[r4 / 2 + 1]) : "l"(a23), "l"(b2));
            }
        }
        __syncthreads();
    }

    float bmv = bm[tid];
    #pragma unroll
    for (int r = 0; r < GTM; r += 2) {
        unsigned long long v = acc2[r / 2];
        float lo = __uint_as_float((unsigned)v);
        float hi = __uint_as_float((unsigned)(v >> 32));
        int row = row0 + r;
        if (row < S)     out[(size_t)row * D + tid]       = lo + g_sumg[row] * bmv;
        if (row + 1 < S) out[(size_t)(row + 1) * D + tid] = hi + g_sumg[row + 1] * bmv;
    }
}

extern "C" void kernel_launch(void* const* d_in, const int* in_sizes, int n_in,
                              void* d_out, int out_size) {
    const float* x       = (const float*)d_in[0];
    const float* weights = (const float*)d_in[1];
    const float* Wg      = (const float*)d_in[2];
    const float* bg      = (const float*)d_in[3];
    const float* Wm      = (const float*)d_in[4];
    const float* bm      = (const float*)d_in[5];
    const float* p       = (const float*)d_in[6];
    const int*   index   = (const int*)d_in[7];
    float* out = (float*)d_out;

    int N = in_sizes[7];
    int S = out_size / D;

    segstart_kernel<<<(N + 255) / 256, 256>>>(index, N, S);
    fused_kernel<<<(S * 32 + 127) / 128, 128>>>(x, weights, Wg, bg, p, S);
    gemm_kernel<<<(S + GTM - 1) / GTM, 256>>>(Wm, bm, out, S);
}